// round 1
// baseline (speedup 1.0000x reference)
#include <cuda_runtime.h>
#include <cstdint>

// GINConv: out = SegmentSum_{CSR}(X[col]) @ W
// N=100000 nodes, DEG=16, D=128. Two kernels:
//   1) agg_kernel: warp-per-node gather-sum (L2-resident X) -> g_xprime scratch
//   2) gemm_tf32:  [N,128]x[128,128] TF32 tensor-core GEMM, 128x128 CTA tile

#define MAX_NODES 100000
#define D 128

// 51.2 MB static scratch (allocation-free per harness rules)
__device__ float g_xprime[(size_t)MAX_NODES * D];

// ---------------------------------------------------------------------------
// Kernel 1: aggregation. One warp per node; each lane owns 4 of 128 dims
// (float4). Gathers are broadcast-index, fully coalesced 512B rows; X fits in
// L2 so steady-state this is L2-throughput bound.
// ---------------------------------------------------------------------------
__global__ void agg_kernel(const float* __restrict__ X,
                           const int* __restrict__ rowptr,
                           const int* __restrict__ colidx,
                           int n_nodes) {
    int warp = (int)((blockIdx.x * (unsigned)blockDim.x + threadIdx.x) >> 5);
    int lane = threadIdx.x & 31;
    if (warp >= n_nodes) return;

    int s = rowptr[warp];
    int e = rowptr[warp + 1];

    const float4* __restrict__ X4 = (const float4*)X;
    float4 acc = make_float4(0.f, 0.f, 0.f, 0.f);

    int i = s;
    // 4-way batched loads for MLP
    for (; i + 4 <= e; i += 4) {
        int c0 = colidx[i + 0];
        int c1 = colidx[i + 1];
        int c2 = colidx[i + 2];
        int c3 = colidx[i + 3];
        float4 v0 = X4[(size_t)c0 * 32 + lane];
        float4 v1 = X4[(size_t)c1 * 32 + lane];
        float4 v2 = X4[(size_t)c2 * 32 + lane];
        float4 v3 = X4[(size_t)c3 * 32 + lane];
        acc.x += (v0.x + v1.x) + (v2.x + v3.x);
        acc.y += (v0.y + v1.y) + (v2.y + v3.y);
        acc.z += (v0.z + v1.z) + (v2.z + v3.z);
        acc.w += (v0.w + v1.w) + (v2.w + v3.w);
    }
    for (; i < e; i++) {
        int c = colidx[i];
        float4 v = X4[(size_t)c * 32 + lane];
        acc.x += v.x; acc.y += v.y; acc.z += v.z; acc.w += v.w;
    }

    ((float4*)g_xprime)[(size_t)warp * 32 + lane] = acc;
}

// ---------------------------------------------------------------------------
// Kernel 2: TF32 tensor-core GEMM. C[M,128] = A[M,128] * B[128,128].
// CTA tile 128x128 (full N, full K one-shot), 8 warps in a 4(M) x 2(N) grid,
// each warp computes 32x64 via m16n8k8 tf32 mma. Values are rounded to tf32
// (cvt.rna) once, during the smem fill.
// Bank analysis: A pad=4 -> frag banks (4g+t) mod 32 unique over the warp;
// B pad=8 -> frag banks (8t+g+c) mod 32 unique. Conflict-free.
// ---------------------------------------------------------------------------
#define SA 132  // 128 + 4 pad (floats per A row)
#define SB 136  // 128 + 8 pad (floats per B row)

__device__ __forceinline__ float f2tf32(float x) {
    unsigned y;
    asm("cvt.rna.tf32.f32 %0, %1;" : "=r"(y) : "f"(x));
    return __uint_as_float(y);
}

__device__ __forceinline__ void mma_tf32(float c[4], const unsigned a[4],
                                         const unsigned b[2]) {
    asm volatile(
        "mma.sync.aligned.m16n8k8.row.col.f32.tf32.tf32.f32 "
        "{%0,%1,%2,%3}, {%4,%5,%6,%7}, {%8,%9}, {%0,%1,%2,%3};"
        : "+f"(c[0]), "+f"(c[1]), "+f"(c[2]), "+f"(c[3])
        : "r"(a[0]), "r"(a[1]), "r"(a[2]), "r"(a[3]), "r"(b[0]), "r"(b[1]));
}

__global__ void __launch_bounds__(256, 1)
gemm_tf32_kernel(const float* __restrict__ W, float* __restrict__ out,
                 int n_nodes) {
    extern __shared__ float smem[];
    float* As = smem;             // [128][SA]
    float* Bs = smem + 128 * SA;  // [128][SB]

    const int tid = threadIdx.x;
    const int lane = tid & 31;
    const int warp = tid >> 5;
    const int g = lane >> 2;   // group id (0..7)
    const int t = lane & 3;    // thread-in-group (0..3)

    const int block_row = blockIdx.x * 128;

    // --- fill Bs (weights, [k][n] row-major), tf32-rounded ---
    #pragma unroll
    for (int i = 0; i < 16; i++) {
        int idx = i * 256 + tid;          // float4 index over 128x128
        int k = idx >> 5;                 // row
        int n4 = idx & 31;                // float4 col
        float4 v = ((const float4*)W)[idx];
        float4 w = make_float4(f2tf32(v.x), f2tf32(v.y), f2tf32(v.z), f2tf32(v.w));
        *(float4*)(Bs + k * SB + n4 * 4) = w;
    }
    // --- fill As (aggregated features), tf32-rounded, zero-pad OOB rows ---
    #pragma unroll
    for (int i = 0; i < 16; i++) {
        int idx = i * 256 + tid;
        int r = idx >> 5;
        int c4 = idx & 31;
        int gr = block_row + r;
        float4 v = make_float4(0.f, 0.f, 0.f, 0.f);
        if (gr < n_nodes) v = ((const float4*)g_xprime)[(size_t)gr * 32 + c4];
        float4 w = make_float4(f2tf32(v.x), f2tf32(v.y), f2tf32(v.z), f2tf32(v.w));
        *(float4*)(As + r * SA + c4 * 4) = w;
    }
    __syncthreads();

    // warp tile: 32 (M) x 64 (N)
    const int warp_row = (warp & 3) * 32;   // 0,32,64,96
    const int warp_col = (warp >> 2) * 64;  // 0,64

    float c[2][8][4];
    #pragma unroll
    for (int mi = 0; mi < 2; mi++)
        #pragma unroll
        for (int ni = 0; ni < 8; ni++)
            #pragma unroll
            for (int j = 0; j < 4; j++) c[mi][ni][j] = 0.f;

    #pragma unroll
    for (int k0 = 0; k0 < 128; k0 += 8) {
        unsigned a[2][4];
        #pragma unroll
        for (int mi = 0; mi < 2; mi++) {
            int r0 = warp_row + mi * 16 + g;
            a[mi][0] = __float_as_uint(As[r0 * SA + k0 + t]);
            a[mi][1] = __float_as_uint(As[(r0 + 8) * SA + k0 + t]);
            a[mi][2] = __float_as_uint(As[r0 * SA + k0 + t + 4]);
            a[mi][3] = __float_as_uint(As[(r0 + 8) * SA + k0 + t + 4]);
        }
        unsigned b[8][2];
        #pragma unroll
        for (int ni = 0; ni < 8; ni++) {
            int cn = warp_col + ni * 8 + g;
            b[ni][0] = __float_as_uint(Bs[(k0 + t) * SB + cn]);
            b[ni][1] = __float_as_uint(Bs[(k0 + t + 4) * SB + cn]);
        }
        #pragma unroll
        for (int mi = 0; mi < 2; mi++)
            #pragma unroll
            for (int ni = 0; ni < 8; ni++)
                mma_tf32(c[mi][ni], a[mi], b[ni]);
    }

    // epilogue: c0,c1 -> (row g, cols 2t,2t+1); c2,c3 -> (row g+8)
    #pragma unroll
    for (int mi = 0; mi < 2; mi++) {
        int r_lo = block_row + warp_row + mi * 16 + g;
        int r_hi = r_lo + 8;
        #pragma unroll
        for (int ni = 0; ni < 8; ni++) {
            int col = warp_col + ni * 8 + 2 * t;
            if (r_lo < n_nodes)
                *(float2*)(out + (size_t)r_lo * 128 + col) =
                    make_float2(c[mi][ni][0], c[mi][ni][1]);
            if (r_hi < n_nodes)
                *(float2*)(out + (size_t)r_hi * 128 + col) =
                    make_float2(c[mi][ni][2], c[mi][ni][3]);
        }
    }
}

// ---------------------------------------------------------------------------
extern "C" void kernel_launch(void* const* d_in, const int* in_sizes, int n_in,
                              void* d_out, int out_size) {
    const float* X      = (const float*)d_in[0];
    const float* W      = (const float*)d_in[1];
    const int*   rowptr = (const int*)d_in[2];
    const int*   colidx = (const int*)d_in[3];
    float*       out    = (float*)d_out;

    int n_nodes = in_sizes[2] - 1;
    if (n_nodes > MAX_NODES) n_nodes = MAX_NODES;

    // kernel 1: aggregation (8 warps / block)
    int agg_blocks = (n_nodes + 7) / 8;
    agg_kernel<<<agg_blocks, 256>>>(X, rowptr, colidx, n_nodes);

    // kernel 2: TF32 GEMM
    static const size_t smem_bytes = (size_t)(128 * SA + 128 * SB) * sizeof(float);
    cudaFuncSetAttribute(gemm_tf32_kernel,
                         cudaFuncAttributeMaxDynamicSharedMemorySize,
                         (int)smem_bytes);
    int gemm_blocks = (n_nodes + 127) / 128;
    gemm_tf32_kernel<<<gemm_blocks, 256, smem_bytes>>>(W, out, n_nodes);
}